// round 1
// baseline (speedup 1.0000x reference)
#include <cuda_runtime.h>
#include <cuda_bf16.h>

// RoiAlign: fm (1,256,50,50) f32, proposals (1024,4) f32 -> out (1024,256,7,7) f32
// Reference double-applies SCALE (1/16 twice => /256). roi_w/h clamp to >=1.
// Separable formulation: out[oy][ox] = sum_{y,x} Wy[oy][y]*Wx[ox][x]*patch[y][x]
// with Wy[oy][r] = 0.5*sum over the bin's 2 subsamples of their bilinear weight at row r.

#define C_CH  256
#define HH    50
#define WW    50
#define OUTSZ 7
#define SSAMP 14   // OUT * SR
#define SPAN  4    // max patch extent per axis handled by fast path

__global__ __launch_bounds__(256, 2)
void roi_align_kernel(const float* __restrict__ fm,
                      const float* __restrict__ proposals,
                      float* __restrict__ out)
{
    const int n   = blockIdx.x;
    const int tid = threadIdx.x;

    __shared__ float s_hy[SSAMP], s_ly[SSAMP], s_hx[SSAMP], s_lx[SSAMP];
    __shared__ int   s_iy0[SSAMP], s_iy1[SSAMP], s_ix0[SSAMP], s_ix1[SSAMP];
    __shared__ float sWy[OUTSZ][SPAN], sWx[OUTSZ][SPAN];
    __shared__ int   s_base[2];     // [0]=ybase, [1]=xbase
    __shared__ int   s_okArr[2];
    __shared__ int   s_yoff[SPAN];  // clamped row offsets (already *WW)
    __shared__ int   s_xoff[SPAN];  // clamped col offsets
    __shared__ __align__(16) float s_stage[64 * 49];

    // ---------- Phase A: per-box axis interpolation params (28 threads) ----------
    if (tid < 2 * SSAMP) {
        const bool isY = tid < SSAMP;
        const int  s   = isY ? tid : tid - SSAMP;
        float4 p = reinterpret_cast<const float4*>(proposals)[n];
        const float sc = 0.0625f;
        // reference: proposals*SCALE outside, then boxes*scale inside _roi_align
        float x1 = (p.x * sc) * sc, y1v = (p.y * sc) * sc;
        float x2 = (p.z * sc) * sc, y2v = (p.w * sc) * sc;
        float roiw = fmaxf(x2 - x1, 1.0f);
        float roih = fmaxf(y2v - y1v, 1.0f);
        float binw = roiw / 7.0f;
        float binh = roih / 7.0f;
        float g = ((float)s + 0.5f) * 0.5f;                  // (s+0.5)/SR
        float v = isY ? (y1v + binh * g) : (x1 + binw * g);
        const int L = isY ? HH : WW;                          // both 50
        bool valid = (v >= -1.0f) && (v <= (float)L);
        float vc = fminf(fmaxf(v, 0.0f), (float)(L - 1));
        int i0 = min((int)floorf(vc), L - 1);
        int i1 = min(i0 + 1, L - 1);
        float l = vc - (float)i0;
        float h = 1.0f - l;
        if (!valid) { h = 0.0f; l = 0.0f; }
        if (isY) { s_iy0[s] = i0; s_iy1[s] = i1; s_hy[s] = h; s_ly[s] = l; }
        else     { s_ix0[s] = i0; s_ix1[s] = i1; s_hx[s] = h; s_lx[s] = l; }
    }
    __syncthreads();

    // ---------- patch bounds per axis ----------
    if (tid < 2) {
        const int* a0 = (tid == 0) ? s_iy0 : s_ix0;
        const int* a1 = (tid == 0) ? s_iy1 : s_ix1;
        int mn = 1 << 30, mx = -1;
        #pragma unroll
        for (int s = 0; s < SSAMP; s++) { mn = min(mn, a0[s]); mx = max(mx, a1[s]); }
        s_base[tid]  = mn;
        s_okArr[tid] = ((mx - mn) < SPAN) ? 1 : 0;
    }
    __syncthreads();

    const bool ok = (s_okArr[0] != 0) && (s_okArr[1] != 0);

    // ---------- build combined separable bin weights ----------
    if (ok) {
        if (tid < OUTSZ) {                          // Wy rows, 7 threads (warp 0)
            float w[SPAN] = {0.f, 0.f, 0.f, 0.f};
            int base = s_base[0];
            #pragma unroll
            for (int k = 0; k < 2; k++) {
                int s = 2 * tid + k;
                w[s_iy0[s] - base] += 0.5f * s_hy[s];
                w[s_iy1[s] - base] += 0.5f * s_ly[s];
            }
            #pragma unroll
            for (int j = 0; j < SPAN; j++) sWy[tid][j] = w[j];
        } else if (tid >= 32 && tid < 32 + OUTSZ) { // Wx rows, 7 threads (warp 1)
            int o = tid - 32;
            float w[SPAN] = {0.f, 0.f, 0.f, 0.f};
            int base = s_base[1];
            #pragma unroll
            for (int k = 0; k < 2; k++) {
                int s = 2 * o + k;
                w[s_ix0[s] - base] += 0.5f * s_hx[s];
                w[s_ix1[s] - base] += 0.5f * s_lx[s];
            }
            #pragma unroll
            for (int j = 0; j < SPAN; j++) sWx[o][j] = w[j];
        } else if (tid >= 64 && tid < 64 + SPAN) {
            s_yoff[tid - 64] = min(s_base[0] + (tid - 64), HH - 1) * WW;
        } else if (tid >= 96 && tid < 96 + SPAN) {
            s_xoff[tid - 96] = min(s_base[1] + (tid - 96), WW - 1);
        }
    }
    __syncthreads();

    const float* fmc = fm + (size_t)tid * (HH * WW);

    if (ok) {
        // ---------- fast separable path: thread = channel ----------
        float wx[OUTSZ][SPAN];
        #pragma unroll
        for (int o = 0; o < OUTSZ; o++)
            #pragma unroll
            for (int j = 0; j < SPAN; j++) wx[o][j] = sWx[o][j];

        const int xo0 = s_xoff[0], xo1 = s_xoff[1], xo2 = s_xoff[2], xo3 = s_xoff[3];

        float acc[OUTSZ][OUTSZ];
        #pragma unroll
        for (int a = 0; a < OUTSZ; a++)
            #pragma unroll
            for (int b = 0; b < OUTSZ; b++) acc[a][b] = 0.0f;

        #pragma unroll
        for (int y = 0; y < SPAN; y++) {
            const float* rp = fmc + s_yoff[y];
            float r0 = rp[xo0], r1 = rp[xo1], r2 = rp[xo2], r3 = rp[xo3];
            float sx[OUTSZ];
            #pragma unroll
            for (int o = 0; o < OUTSZ; o++)
                sx[o] = r0 * wx[o][0] + r1 * wx[o][1] + r2 * wx[o][2] + r3 * wx[o][3];
            #pragma unroll
            for (int oy = 0; oy < OUTSZ; oy++) {
                float wyv = sWy[oy][y];
                #pragma unroll
                for (int ox = 0; ox < OUTSZ; ox++)
                    acc[oy][ox] += wyv * sx[ox];
            }
        }

        // ---------- staged, coalesced stores (64 channels per chunk) ----------
        #pragma unroll 1
        for (int chunk = 0; chunk < 4; chunk++) {
            __syncthreads();
            if ((tid >> 6) == chunk) {
                int cl = tid & 63;
                #pragma unroll
                for (int oy = 0; oy < OUTSZ; oy++)
                    #pragma unroll
                    for (int ox = 0; ox < OUTSZ; ox++)
                        s_stage[cl * 49 + oy * 7 + ox] = acc[oy][ox];
            }
            __syncthreads();
            float4* dst = reinterpret_cast<float4*>(
                out + ((size_t)n * C_CH + (size_t)chunk * 64) * 49);
            const float4* src = reinterpret_cast<const float4*>(s_stage);
            for (int i = tid; i < (64 * 49) / 4; i += 256)
                dst[i] = src[i];
        }
    } else {
        // ---------- general fallback (block-uniform branch, never hot here) ----------
        float* outc = out + ((size_t)n * C_CH + tid) * 49;
        for (int oy = 0; oy < OUTSZ; oy++) {
            for (int ox = 0; ox < OUTSZ; ox++) {
                float a = 0.0f;
                #pragma unroll
                for (int ky = 0; ky < 2; ky++) {
                    int sy = 2 * oy + ky;
                    int y0 = s_iy0[sy] * WW, y1i = s_iy1[sy] * WW;
                    float hy = s_hy[sy], ly = s_ly[sy];
                    #pragma unroll
                    for (int kx = 0; kx < 2; kx++) {
                        int sxi = 2 * ox + kx;
                        int x0 = s_ix0[sxi], x1i = s_ix1[sxi];
                        float hx = s_hx[sxi], lx = s_lx[sxi];
                        a += hy * (hx * fmc[y0 + x0]  + lx * fmc[y0 + x1i])
                           + ly * (hx * fmc[y1i + x0] + lx * fmc[y1i + x1i]);
                    }
                }
                outc[oy * 7 + ox] = a * 0.25f;
            }
        }
    }
}

extern "C" void kernel_launch(void* const* d_in, const int* in_sizes, int n_in,
                              void* d_out, int out_size) {
    const float* fm    = (const float*)d_in[0];   // (1,256,50,50) f32
    const float* props = (const float*)d_in[1];   // (1024,4) f32
    float* out         = (float*)d_out;           // (1024,256,7,7) f32
    int N = in_sizes[1] / 4;
    roi_align_kernel<<<N, 256>>>(fm, props, out);
}